// round 10
// baseline (speedup 1.0000x reference)
#include <cuda_runtime.h>
#include <cuda_fp16.h>
#include <math.h>

#define NN 200000
#define EE 6400000
#define MM 10000
#define SHARDS 4
#define SSLOT 32            // slots per shard; P(Poisson(8) >= 32) ~ 7e-11
#define SLOTS 128           // SHARDS * SSLOT, per node
#define BUCKET_BLOCKS 6250  // 6.4M edges / 4-per-thread / 256
#define GEMM_BLOCKS 3125    // 200000 / 64
#define SCALE_BLOCKS 3125   // 200000*16 floats / 4 / 256
#define ZERO_BLOCKS 3125    // 800000 counters / 256

// ---------------- device scratch (no allocations allowed) ----------------
__device__ __align__(16) int    g_cnt[NN * SHARDS];           // sharded in-degree
__device__ __align__(16) int    g_slot[(size_t)NN * SLOTS];   // sharded padded adjacency
__device__                 char g_need[NN];
__device__ __align__(16) float  g_h1[(size_t)NN * 16];    // x@W1 (raw, fp32)
__device__ __align__(16) __half g_h1h[(size_t)NN * 16];   // dinv * (x@W1), fp16
__device__ __align__(16) float  g_hw2[(size_t)NN * 2];    // dinv * (relu(l1) @ W2)
__device__ __align__(16) float  g_bp[MM * 5];
__device__ __align__(16) unsigned g_minmax[2];

// ordered-uint encoding so unsigned atomicMin/Max give float min/max
__device__ __forceinline__ unsigned fenc(float f) {
    unsigned u = __float_as_uint(f);
    return (u & 0x80000000u) ? ~u : (u | 0x80000000u);
}
__device__ __forceinline__ float fdec(unsigned u) {
    return (u & 0x80000000u) ? __uint_as_float(u & 0x7fffffffu)
                             : __uint_as_float(~u);
}

// map flat edge index i -> sharded slot offset for node base (cum counts)
__device__ __forceinline__ int slot_index(int i, int c1, int c2, int c3) {
    // shard 0: [0,c1) shard1: [c1,c2) shard2: [c2,c3) shard3: [c3,deg)
    int j3 = (i >= c3);
    int j2 = (i >= c2) & !j3;
    int j1 = (i >= c1) & !(j2 | j3);
    int pos = i - (j1 ? c1 : 0) - (j2 ? c2 : 0) - (j3 ? c3 : 0);
    int shard = j1 + 2 * j2 + 3 * j3;
    return shard * SSLOT + pos;
}

// ---------------- kernels ----------------

__global__ void k_zero() {
    int i = blockIdx.x * blockDim.x + threadIdx.x;   // 0 .. 800K-1
    g_cnt[i] = 0;
    if (i < NN) g_need[i] = ((i % 20) == 0) ? 1 : 0;
    if (i == 0) { g_minmax[0] = 0xFFFFFFFFu; g_minmax[1] = 0u; }
}

// Fused: sharded bucket scatter (blocks [0, BUCKET_BLOCKS)) || x@W1 GEMM (rest).
// Shard choice (t+k)&3 decorrelates edges of the same dst -> contention/addr
// drops from ~32 to ~8, breaking the LTS per-address serialization.
__global__ void k_bucket_gemm(const int* __restrict__ src,
                              const int* __restrict__ dst,
                              const float* __restrict__ x,
                              const float* __restrict__ W1) {
    __shared__ __align__(16) float sx[64 * 100];
    __shared__ __align__(16) float sw[100 * 16];
    int t = threadIdx.x;
    if (blockIdx.x < BUCKET_BLOCKS) {
        int i = blockIdx.x * 256 + t;          // int4 index, 6250*256 = 1.6M exactly
        int4 s4 = ((const int4*)src)[i];
        int4 d4 = ((const int4*)dst)[i];
        int p, sh;
        sh = t & 3;
        p = atomicAdd(&g_cnt[d4.x * SHARDS + sh], 1);
        g_slot[(size_t)d4.x * SLOTS + sh * SSLOT + p] = s4.x;
        if (d4.x % 20 == 0) g_need[s4.x] = 1;
        sh = (t + 1) & 3;
        p = atomicAdd(&g_cnt[d4.y * SHARDS + sh], 1);
        g_slot[(size_t)d4.y * SLOTS + sh * SSLOT + p] = s4.y;
        if (d4.y % 20 == 0) g_need[s4.y] = 1;
        sh = (t + 2) & 3;
        p = atomicAdd(&g_cnt[d4.z * SHARDS + sh], 1);
        g_slot[(size_t)d4.z * SLOTS + sh * SSLOT + p] = s4.z;
        if (d4.z % 20 == 0) g_need[s4.z] = 1;
        sh = (t + 3) & 3;
        p = atomicAdd(&g_cnt[d4.w * SHARDS + sh], 1);
        g_slot[(size_t)d4.w * SLOTS + sh * SSLOT + p] = s4.w;
        if (d4.w % 20 == 0) g_need[s4.w] = 1;
        return;
    }
    int b = blockIdx.x - BUCKET_BLOCKS;
    size_t row0 = (size_t)b * 64;

    const float4* xg = (const float4*)(x + row0 * 100);
    float4* sx4 = (float4*)sx;
#pragma unroll
    for (int i = 0; i < 7; i++) { int idx = t + i * 256; if (idx < 1600) sx4[idx] = xg[idx]; }
    const float4* wg = (const float4*)W1;
    float4* sw4 = (float4*)sw;
#pragma unroll
    for (int i = 0; i < 2; i++) { int idx = t + i * 256; if (idx < 400) sw4[idx] = wg[idx]; }
    __syncthreads();

    int j = t & 15, rg = t >> 4;
    float a0 = 0.f, a1 = 0.f, a2 = 0.f, a3 = 0.f;
#pragma unroll 4
    for (int k = 0; k < 100; k++) {
        float w = sw[k * 16 + j];
        a0 += sx[(rg +  0) * 100 + k] * w;
        a1 += sx[(rg + 16) * 100 + k] * w;
        a2 += sx[(rg + 32) * 100 + k] * w;
        a3 += sx[(rg + 48) * 100 + k] * w;
    }
    int r0 = (int)row0;
    g_h1[(size_t)(r0 + rg +  0) * 16 + j] = a0;
    g_h1[(size_t)(r0 + rg + 16) * 16 + j] = a1;
    g_h1[(size_t)(r0 + rg + 32) * 16 + j] = a2;
    g_h1[(size_t)(r0 + rg + 48) * 16 + j] = a3;
}

// h1h = fp16(dinv * h1). Counts are final only after bucketing.
__global__ void k_scale() {
    int i = blockIdx.x * 256 + threadIdx.x;   // float4 index into g_h1 (800000 total)
    int row = i >> 2;
    int4 c4 = __ldg((const int4*)&g_cnt[row * SHARDS]);
    float dv = rsqrtf((float)(c4.x + c4.y + c4.z + c4.w) + 1.0f);
    float4 v = ((const float4*)g_h1)[i];
    __half2 ha = __floats2half2_rn(v.x * dv, v.y * dv);
    __half2 hb = __floats2half2_rn(v.z * dv, v.w * dv);
    uint2 o;
    o.x = *reinterpret_cast<unsigned*>(&ha);
    o.y = *reinterpret_cast<unsigned*>(&hb);
    ((uint2*)g_h1h)[i] = o;
}

// Pull aggregation layer 1 (needed nodes only), fused bias+relu+(@W2)+dinv.
// One warp per node; 2 lanes per edge (each lane one 16B half-row = 8 fp16),
// 16 independent edge gathers in flight per iteration. fp32 accumulate.
__global__ void k_pass1(const float* __restrict__ b1, const float* __restrict__ W2) {
    int warp = (blockIdx.x * blockDim.x + threadIdx.x) >> 5;
    if (warp >= NN) return;
    int node = warp;
    if (!g_need[node]) return;
    int lane = threadIdx.x & 31;
    int4 c4 = __ldg((const int4*)&g_cnt[node * SHARDS]);
    int c1 = c4.x, c2 = c1 + c4.y, c3 = c2 + c4.z;
    int ndeg = c3 + c4.w;
    size_t off = (size_t)node * SLOTS;
    int eg = lane >> 1, c = lane & 1;     // eg: edge slot 0..15, c: half selector
    const unsigned FULL = 0xffffffffu;

    float acc[8];
#pragma unroll
    for (int k = 0; k < 8; k++) acc[k] = 0.f;

#pragma unroll 2
    for (int i = eg; i < ndeg; i += 16) {
        int s = __ldg(&g_slot[off + slot_index(i, c1, c2, c3)]);
        uint4 v = __ldg((const uint4*)(g_h1h + (size_t)s * 16 + c * 8));
        float2 f0 = __half22float2(*reinterpret_cast<__half2*>(&v.x));
        float2 f1 = __half22float2(*reinterpret_cast<__half2*>(&v.y));
        float2 f2 = __half22float2(*reinterpret_cast<__half2*>(&v.z));
        float2 f3 = __half22float2(*reinterpret_cast<__half2*>(&v.w));
        acc[0] += f0.x; acc[1] += f0.y; acc[2] += f1.x; acc[3] += f1.y;
        acc[4] += f2.x; acc[5] += f2.y; acc[6] += f3.x; acc[7] += f3.y;
    }
    // reduce over the 16 edge slots (keep c=0/1 halves separate)
#pragma unroll
    for (int o = 2; o <= 16; o <<= 1) {
#pragma unroll
        for (int k = 0; k < 8; k++) acc[k] += __shfl_xor_sync(FULL, acc[k], o);
    }
    // self term (h1h already has dinv folded in)
    {
        uint4 v = __ldg((const uint4*)(g_h1h + (size_t)node * 16 + c * 8));
        float2 f0 = __half22float2(*reinterpret_cast<__half2*>(&v.x));
        float2 f1 = __half22float2(*reinterpret_cast<__half2*>(&v.y));
        float2 f2 = __half22float2(*reinterpret_cast<__half2*>(&v.z));
        float2 f3 = __half22float2(*reinterpret_cast<__half2*>(&v.w));
        acc[0] += f0.x; acc[1] += f0.y; acc[2] += f1.x; acc[3] += f1.y;
        acc[4] += f2.x; acc[5] += f2.y; acc[6] += f3.x; acc[7] += f3.y;
    }
    float dv = rsqrtf((float)ndeg + 1.0f);
    float p0 = 0.f, p1 = 0.f;
#pragma unroll
    for (int k = 0; k < 8; k++) {
        int h = c * 8 + k;
        float rk = fmaxf(dv * acc[k] + __ldg(&b1[h]), 0.f);
        p0 += rk * __ldg(&W2[h * 2 + 0]);
        p1 += rk * __ldg(&W2[h * 2 + 1]);
    }
    p0 += __shfl_xor_sync(FULL, p0, 1);
    p1 += __shfl_xor_sync(FULL, p1, 1);
    if (lane == 0) {
        g_hw2[(size_t)node * 2 + 0] = dv * p0;
        g_hw2[(size_t)node * 2 + 1] = dv * p1;
    }
}

// Layer-2 aggregation only for nodes d=20m, fused bias + log_softmax + BP + min/max.
__global__ void k_pass2(const float* __restrict__ tE, const float* __restrict__ cE,
                        const float* __restrict__ pE, const float* __restrict__ b2) {
    int warp = (blockIdx.x * blockDim.x + threadIdx.x) >> 5;
    int lane = threadIdx.x & 31;
    if (warp >= MM) return;
    int m = warp;
    int d = m * 20;
    int4 c4 = __ldg((const int4*)&g_cnt[d * SHARDS]);
    int c1 = c4.x, c2 = c1 + c4.y, c3 = c2 + c4.z;
    int ndeg = c3 + c4.w;
    size_t off = (size_t)d * SLOTS;
    float a0 = 0.f, a1 = 0.f;
    for (int i = lane; i < ndeg; i += 32) {
        int s = __ldg(&g_slot[off + slot_index(i, c1, c2, c3)]);
        float2 v = *reinterpret_cast<const float2*>(&g_hw2[(size_t)s * 2]);
        a0 += v.x; a1 += v.y;
    }
    const unsigned FULL = 0xffffffffu;
#pragma unroll
    for (int o = 16; o > 0; o >>= 1) {
        a0 += __shfl_xor_sync(FULL, a0, o);
        a1 += __shfl_xor_sync(FULL, a1, o);
    }
    if (lane == 0) {
        float2 sv = *reinterpret_cast<const float2*>(&g_hw2[(size_t)d * 2]);
        a0 += sv.x; a1 += sv.y;
        float dv = rsqrtf((float)ndeg + 1.0f);
        float z0 = dv * a0 + __ldg(&b2[0]);
        float z1 = dv * a1 + __ldg(&b2[1]);
        float mx = fmaxf(z0, z1);
        float lse = mx + logf(expf(z0 - mx) + expf(z1 - mx));
        float ls0 = z0 - lse, ls1 = z1 - lse;
        float v0 = __ldg(&tE[m]), v1 = __ldg(&cE[m]), v2 = __ldg(&pE[m]);
        g_bp[m * 5 + 0] = v0;
        g_bp[m * 5 + 1] = v1;
        g_bp[m * 5 + 2] = v2;
        g_bp[m * 5 + 3] = ls0;
        g_bp[m * 5 + 4] = ls1;
        float mn  = fminf(fminf(v0, v1), fminf(v2, fminf(ls0, ls1)));
        float mxv = fmaxf(fmaxf(v0, v1), fmaxf(v2, fmaxf(ls0, ls1)));
        atomicMin(&g_minmax[0], fenc(mn));
        atomicMax(&g_minmax[1], fenc(mxv));
    }
}

// min-max normalize + 5->80->10->1 MLP + sigmoid
__global__ void k_mlp(const float* __restrict__ W1, const float* __restrict__ b1,
                      const float* __restrict__ W2, const float* __restrict__ b2,
                      const float* __restrict__ W3, const float* __restrict__ b3,
                      float* __restrict__ out) {
    __shared__ float sW1[400], sb1[80], sW2[800], sb2[10], sW3[10];
    __shared__ float sb3v, smn, ssc;
    int t = threadIdx.x;
    for (int i = t; i < 400; i += 256) sW1[i] = W1[i];
    for (int i = t; i < 80;  i += 256) sb1[i] = b1[i];
    for (int i = t; i < 800; i += 256) sW2[i] = W2[i];
    if (t < 10) { sb2[t] = b2[t]; sW3[t] = W3[t]; }
    if (t == 0) {
        sb3v = b3[0];
        smn = fdec(g_minmax[0]);
        float mxv = fdec(g_minmax[1]);
        ssc = 1.0f / (mxv - smn);
    }
    __syncthreads();
    int m = blockIdx.x * blockDim.x + t;
    if (m >= MM) return;
    float in[5];
#pragma unroll
    for (int i = 0; i < 5; i++) in[i] = (g_bp[m * 5 + i] - smn) * ssc;
    float h2[10];
#pragma unroll
    for (int q = 0; q < 10; q++) h2[q] = sb2[q];
    for (int o = 0; o < 80; o++) {
        float a = sb1[o];
#pragma unroll
        for (int i = 0; i < 5; i++) a += in[i] * sW1[i * 80 + o];
        a = fmaxf(a, 0.f);
#pragma unroll
        for (int q = 0; q < 10; q++) h2[q] += a * sW2[o * 10 + q];
    }
    float v = sb3v;
#pragma unroll
    for (int q = 0; q < 10; q++) v += fmaxf(h2[q], 0.f) * sW3[q];
    out[m] = 1.0f / (1.0f + expf(-v));
}

// ---------------- launch ----------------
extern "C" void kernel_launch(void* const* d_in, const int* in_sizes, int n_in,
                              void* d_out, int out_size) {
    const int*   ei   = (const int*)d_in[0];    // batch1_edge_index [2,E]
    const float* x    = (const float*)d_in[1];  // batch1_x [N,100]
    const float* tE   = (const float*)d_in[4];
    const float* cE   = (const float*)d_in[5];
    const float* pE   = (const float*)d_in[6];
    const float* ghW1 = (const float*)d_in[8];
    const float* ghb1 = (const float*)d_in[9];
    const float* ghW2 = (const float*)d_in[10];
    const float* ghb2 = (const float*)d_in[11];
    const float* mW1  = (const float*)d_in[16];
    const float* mb1  = (const float*)d_in[17];
    const float* mW2  = (const float*)d_in[18];
    const float* mb2  = (const float*)d_in[19];
    const float* mW3  = (const float*)d_in[20];
    const float* mb3  = (const float*)d_in[21];
    // batch2_*, edit_input, gt_* are dead in the reference output — skipped.

    const int* src = ei;
    const int* dst = ei + EE;
    float* out = (float*)d_out;

    k_zero        <<<ZERO_BLOCKS, 256>>>();
    k_bucket_gemm <<<BUCKET_BLOCKS + GEMM_BLOCKS, 256>>>(src, dst, x, ghW1);
    k_scale       <<<SCALE_BLOCKS, 256>>>();
    k_pass1       <<<NN / 8, 256>>>(ghb1, ghW2);
    k_pass2       <<<MM / 8, 256>>>(tE, cE, pE, ghb2);
    k_mlp         <<<(MM + 255) / 256, 256>>>(mW1, mb1, mW2, mb2, mW3, mb3, out);
}

// round 11
// speedup vs baseline: 1.3028x; 1.3028x over previous
#include <cuda_runtime.h>
#include <cuda_fp16.h>
#include <math.h>

#define NN 200000
#define EE 6400000
#define MM 10000
#define SHARDS 4
#define SCAN_CHUNK 2048
#define SCAN_NB 98          // ceil(NN / SCAN_CHUNK)
#define HIST_BLOCKS 6250    // 6.4M edges / 4-per-thread / 256
#define GEMM_BLOCKS 3125    // 200000 / 64
#define SCAT_BLOCKS 6250
#define SCALE_BLOCKS 3125   // 200000*16 floats / 4 / 256
#define SENT (-2147483647 - 1)

// ---------------- device scratch (no allocations allowed) ----------------
__device__ __align__(16) int    g_cnt[NN * SHARDS];   // sharded in-degree counters
__device__ __align__(16) int    g_off[NN];            // packed CSR row offsets
__device__ __align__(16) int    g_cursor[NN * SHARDS];// absolute sub-cursors per shard
__device__ __align__(16) int    g_agg[128];           // scan lookback aggregates
__device__ __align__(16) int    g_csr[EE];            // packed adjacency (25.6MB, L2-resident)
__device__                 char g_need[NN];
__device__ __align__(16) float  g_h1[(size_t)NN * 16];    // x@W1 (raw, fp32)
__device__ __align__(16) __half g_h1h[(size_t)NN * 16];   // dinv * (x@W1), fp16
__device__ __align__(16) float  g_hw2[(size_t)NN * 2];    // dinv * (relu(l1) @ W2)
__device__ __align__(16) float  g_bp[MM * 5];
__device__ __align__(16) unsigned g_minmax[2];

// ordered-uint encoding so unsigned atomicMin/Max give float min/max
__device__ __forceinline__ unsigned fenc(float f) {
    unsigned u = __float_as_uint(f);
    return (u & 0x80000000u) ? ~u : (u | 0x80000000u);
}
__device__ __forceinline__ float fdec(unsigned u) {
    return (u & 0x80000000u) ? __uint_as_float(u & 0x7fffffffu)
                             : __uint_as_float(~u);
}

// ---------------- kernels ----------------

__global__ void k_zero() {
    int i = blockIdx.x * blockDim.x + threadIdx.x;   // 800K threads
    g_cnt[i] = 0;
    if (i < NN) g_need[i] = ((i % 20) == 0) ? 1 : 0;
    if (i < 128) g_agg[i] = SENT;
    if (i == 0) { g_minmax[0] = 0xFFFFFFFFu; g_minmax[1] = 0u; }
}

// Fused: sharded histogram of dst (blocks [0, HIST_BLOCKS)) || x@W1 GEMM.
// Shard (t+k)&3 decorrelates same-dst edges: contention/addr 32 -> ~8.
// atomicAdd result unused -> RED (no-return).
__global__ void k_hist_gemm(const int* __restrict__ dst,
                            const float* __restrict__ x,
                            const float* __restrict__ W1) {
    __shared__ __align__(16) float sx[64 * 100];
    __shared__ __align__(16) float sw[100 * 16];
    int t = threadIdx.x;
    if (blockIdx.x < HIST_BLOCKS) {
        int i = blockIdx.x * 256 + t;          // int4 index, 6250*256 = 1.6M exactly
        int4 d = ((const int4*)dst)[i];
        atomicAdd(&g_cnt[d.x * SHARDS + ( t      & 3)], 1);
        atomicAdd(&g_cnt[d.y * SHARDS + ((t + 1) & 3)], 1);
        atomicAdd(&g_cnt[d.z * SHARDS + ((t + 2) & 3)], 1);
        atomicAdd(&g_cnt[d.w * SHARDS + ((t + 3) & 3)], 1);
        return;
    }
    int b = blockIdx.x - HIST_BLOCKS;
    size_t row0 = (size_t)b * 64;

    const float4* xg = (const float4*)(x + row0 * 100);
    float4* sx4 = (float4*)sx;
#pragma unroll
    for (int i = 0; i < 7; i++) { int idx = t + i * 256; if (idx < 1600) sx4[idx] = xg[idx]; }
    const float4* wg = (const float4*)W1;
    float4* sw4 = (float4*)sw;
#pragma unroll
    for (int i = 0; i < 2; i++) { int idx = t + i * 256; if (idx < 400) sw4[idx] = wg[idx]; }
    __syncthreads();

    int j = t & 15, rg = t >> 4;
    float a0 = 0.f, a1 = 0.f, a2 = 0.f, a3 = 0.f;
#pragma unroll 4
    for (int k = 0; k < 100; k++) {
        float w = sw[k * 16 + j];
        a0 += sx[(rg +  0) * 100 + k] * w;
        a1 += sx[(rg + 16) * 100 + k] * w;
        a2 += sx[(rg + 32) * 100 + k] * w;
        a3 += sx[(rg + 48) * 100 + k] * w;
    }
    int r0 = (int)row0;
    g_h1[(size_t)(r0 + rg +  0) * 16 + j] = a0;
    g_h1[(size_t)(r0 + rg + 16) * 16 + j] = a1;
    g_h1[(size_t)(r0 + rg + 32) * 16 + j] = a2;
    g_h1[(size_t)(r0 + rg + 48) * 16 + j] = a3;
}

// Decoupled-lookback exclusive scan of node degrees (sum of 4 shard counts)
// -> packed g_off + 4 absolute sub-cursors per node partitioning [off, off+deg).
__global__ void k_scan() {
    __shared__ int sh[512];
    __shared__ int s_prefix;
    int b = blockIdx.x, t = threadIdx.x;
    int base = b * SCAN_CHUNK + t * 4;
    int4 c[4]; int deg[4]; int s = 0;
#pragma unroll
    for (int i = 0; i < 4; i++) {
        int idx = base + i;
        if (idx < NN) c[i] = *(const int4*)&g_cnt[idx * SHARDS];
        else          c[i] = make_int4(0, 0, 0, 0);
        deg[i] = c[i].x + c[i].y + c[i].z + c[i].w;
        s += deg[i];
    }
    sh[t] = s; __syncthreads();
    for (int o = 1; o < 512; o <<= 1) {
        int u = (t >= o) ? sh[t - o] : 0;
        __syncthreads();
        sh[t] += u;
        __syncthreads();
    }
    int total = sh[511];
    if (t == 0) {
        s_prefix = 0;
        *(volatile int*)&g_agg[b] = total;   // publish aggregate
        __threadfence();
    }
    __syncthreads();
    int pv = 0;
    if (t < b) {
        int xv;
        do { xv = *(volatile int*)&g_agg[t]; } while (xv == SENT);
        pv = xv;
    }
#pragma unroll
    for (int o = 16; o > 0; o >>= 1) pv += __shfl_xor_sync(0xffffffffu, pv, o);
    if ((t & 31) == 0 && pv != 0) atomicAdd(&s_prefix, pv);
    __syncthreads();
    int ex = sh[t] - s + s_prefix;
#pragma unroll
    for (int i = 0; i < 4; i++) {
        int idx = base + i;
        if (idx < NN) {
            g_off[idx] = ex;
            int4 cur;
            cur.x = ex;
            cur.y = ex + c[i].x;
            cur.z = ex + c[i].x + c[i].y;
            cur.w = ex + c[i].x + c[i].y + c[i].z;
            *(int4*)&g_cursor[idx * SHARDS] = cur;
            ex += deg[i];
        }
    }
}

// Fused: packed scatter with sharded cursors + need-mark (blocks [0,SCAT_BLOCKS))
//        || h1h = fp16(dinv * h1) (rest). Shard formula MUST match k_hist_gemm.
__global__ void k_scatter_scale(const int* __restrict__ src, const int* __restrict__ dst) {
    int t = threadIdx.x;
    if (blockIdx.x < SCAT_BLOCKS) {
        int i = blockIdx.x * 256 + t;
        int4 s4 = ((const int4*)src)[i];
        int4 d4 = ((const int4*)dst)[i];
        int p;
        p = atomicAdd(&g_cursor[d4.x * SHARDS + ( t      & 3)], 1); g_csr[p] = s4.x;
        if (d4.x % 20 == 0) g_need[s4.x] = 1;
        p = atomicAdd(&g_cursor[d4.y * SHARDS + ((t + 1) & 3)], 1); g_csr[p] = s4.y;
        if (d4.y % 20 == 0) g_need[s4.y] = 1;
        p = atomicAdd(&g_cursor[d4.z * SHARDS + ((t + 2) & 3)], 1); g_csr[p] = s4.z;
        if (d4.z % 20 == 0) g_need[s4.z] = 1;
        p = atomicAdd(&g_cursor[d4.w * SHARDS + ((t + 3) & 3)], 1); g_csr[p] = s4.w;
        if (d4.w % 20 == 0) g_need[s4.w] = 1;
        return;
    }
    int b = blockIdx.x - SCAT_BLOCKS;
    int i = b * 256 + t;                 // float4 index into g_h1 (800000 total)
    int row = i >> 2;
    int4 c4 = __ldg((const int4*)&g_cnt[row * SHARDS]);
    float dv = rsqrtf((float)(c4.x + c4.y + c4.z + c4.w) + 1.0f);
    float4 v = ((const float4*)g_h1)[i];
    __half2 ha = __floats2half2_rn(v.x * dv, v.y * dv);
    __half2 hb = __floats2half2_rn(v.z * dv, v.w * dv);
    uint2 o;
    o.x = *reinterpret_cast<unsigned*>(&ha);
    o.y = *reinterpret_cast<unsigned*>(&hb);
    ((uint2*)g_h1h)[i] = o;
}

// Pull aggregation layer 1: 4 nodes per warp, 8 lanes per node.
// Lane k owns half2 column pair (2k, 2k+1); serial accumulation over the
// node's contiguous CSR segment -> NO big shuffle reduction, no index math.
// Fused bias + relu + (@W2) + dinv epilogue (3-stage 2-scalar reduce only).
__global__ void k_pass1(const float* __restrict__ b1, const float* __restrict__ W2) {
    int gw = (blockIdx.x * blockDim.x + threadIdx.x) >> 5;   // warp id, 50000 total
    int lane = threadIdx.x & 31;
    int nl = lane >> 3, k = lane & 7;
    int node = gw * 4 + nl;                                  // exact: 50000*4 = NN
    bool need = g_need[node];
    int4 c4 = __ldg((const int4*)&g_cnt[node * SHARDS]);
    int ndeg = need ? (c4.x + c4.y + c4.z + c4.w) : 0;
    int off  = __ldg(&g_off[node]);
    const unsigned FULL = 0xffffffffu;

    float ax = 0.f, ay = 0.f;
#pragma unroll 4
    for (int i = 0; i < ndeg; i++) {
        int s = __ldg(&g_csr[off + i]);                      // broadcast within group
        __half2 hv = __ldg((const __half2*)(g_h1h + (size_t)s * 16 + 2 * k));
        float2 f = __half22float2(hv);
        ax += f.x; ay += f.y;
    }
    // self term (h1h already has dinv folded in)
    {
        __half2 hv = __ldg((const __half2*)(g_h1h + (size_t)node * 16 + 2 * k));
        float2 f = __half22float2(hv);
        ax += f.x; ay += f.y;
    }
    float dv = rsqrtf((float)ndeg + 1.0f);
    float r0 = fmaxf(dv * ax + __ldg(&b1[2 * k + 0]), 0.f);
    float r1 = fmaxf(dv * ay + __ldg(&b1[2 * k + 1]), 0.f);
    float p0 = r0 * __ldg(&W2[(2 * k + 0) * 2 + 0]) + r1 * __ldg(&W2[(2 * k + 1) * 2 + 0]);
    float p1 = r0 * __ldg(&W2[(2 * k + 0) * 2 + 1]) + r1 * __ldg(&W2[(2 * k + 1) * 2 + 1]);
    // reduce across the 8-lane group (xor 1,2,4 stays inside the group)
    p0 += __shfl_xor_sync(FULL, p0, 1); p1 += __shfl_xor_sync(FULL, p1, 1);
    p0 += __shfl_xor_sync(FULL, p0, 2); p1 += __shfl_xor_sync(FULL, p1, 2);
    p0 += __shfl_xor_sync(FULL, p0, 4); p1 += __shfl_xor_sync(FULL, p1, 4);
    if (k == 0 && need) {
        float2 o; o.x = dv * p0; o.y = dv * p1;
        *(float2*)&g_hw2[(size_t)node * 2] = o;
    }
}

// Layer-2 aggregation only for nodes d=20m, fused bias + log_softmax + BP + min/max.
__global__ void k_pass2(const float* __restrict__ tE, const float* __restrict__ cE,
                        const float* __restrict__ pE, const float* __restrict__ b2) {
    int warp = (blockIdx.x * blockDim.x + threadIdx.x) >> 5;
    int lane = threadIdx.x & 31;
    if (warp >= MM) return;
    int m = warp;
    int d = m * 20;
    int4 c4 = __ldg((const int4*)&g_cnt[d * SHARDS]);
    int ndeg = c4.x + c4.y + c4.z + c4.w;
    int off  = __ldg(&g_off[d]);
    float a0 = 0.f, a1 = 0.f;
    for (int i = lane; i < ndeg; i += 32) {
        int s = __ldg(&g_csr[off + i]);
        float2 v = *reinterpret_cast<const float2*>(&g_hw2[(size_t)s * 2]);
        a0 += v.x; a1 += v.y;
    }
    const unsigned FULL = 0xffffffffu;
#pragma unroll
    for (int o = 16; o > 0; o >>= 1) {
        a0 += __shfl_xor_sync(FULL, a0, o);
        a1 += __shfl_xor_sync(FULL, a1, o);
    }
    if (lane == 0) {
        float2 sv = *reinterpret_cast<const float2*>(&g_hw2[(size_t)d * 2]);
        a0 += sv.x; a1 += sv.y;
        float dv = rsqrtf((float)ndeg + 1.0f);
        float z0 = dv * a0 + __ldg(&b2[0]);
        float z1 = dv * a1 + __ldg(&b2[1]);
        float mx = fmaxf(z0, z1);
        float lse = mx + logf(expf(z0 - mx) + expf(z1 - mx));
        float ls0 = z0 - lse, ls1 = z1 - lse;
        float v0 = __ldg(&tE[m]), v1 = __ldg(&cE[m]), v2 = __ldg(&pE[m]);
        g_bp[m * 5 + 0] = v0;
        g_bp[m * 5 + 1] = v1;
        g_bp[m * 5 + 2] = v2;
        g_bp[m * 5 + 3] = ls0;
        g_bp[m * 5 + 4] = ls1;
        float mn  = fminf(fminf(v0, v1), fminf(v2, fminf(ls0, ls1)));
        float mxv = fmaxf(fmaxf(v0, v1), fmaxf(v2, fmaxf(ls0, ls1)));
        atomicMin(&g_minmax[0], fenc(mn));
        atomicMax(&g_minmax[1], fenc(mxv));
    }
}

// min-max normalize + 5->80->10->1 MLP + sigmoid
__global__ void k_mlp(const float* __restrict__ W1, const float* __restrict__ b1,
                      const float* __restrict__ W2, const float* __restrict__ b2,
                      const float* __restrict__ W3, const float* __restrict__ b3,
                      float* __restrict__ out) {
    __shared__ float sW1[400], sb1[80], sW2[800], sb2[10], sW3[10];
    __shared__ float sb3v, smn, ssc;
    int t = threadIdx.x;
    for (int i = t; i < 400; i += 256) sW1[i] = W1[i];
    for (int i = t; i < 80;  i += 256) sb1[i] = b1[i];
    for (int i = t; i < 800; i += 256) sW2[i] = W2[i];
    if (t < 10) { sb2[t] = b2[t]; sW3[t] = W3[t]; }
    if (t == 0) {
        sb3v = b3[0];
        smn = fdec(g_minmax[0]);
        float mxv = fdec(g_minmax[1]);
        ssc = 1.0f / (mxv - smn);
    }
    __syncthreads();
    int m = blockIdx.x * blockDim.x + t;
    if (m >= MM) return;
    float in[5];
#pragma unroll
    for (int i = 0; i < 5; i++) in[i] = (g_bp[m * 5 + i] - smn) * ssc;
    float h2[10];
#pragma unroll
    for (int q = 0; q < 10; q++) h2[q] = sb2[q];
    for (int o = 0; o < 80; o++) {
        float a = sb1[o];
#pragma unroll
        for (int i = 0; i < 5; i++) a += in[i] * sW1[i * 80 + o];
        a = fmaxf(a, 0.f);
#pragma unroll
        for (int q = 0; q < 10; q++) h2[q] += a * sW2[o * 10 + q];
    }
    float v = sb3v;
#pragma unroll
    for (int q = 0; q < 10; q++) v += fmaxf(h2[q], 0.f) * sW3[q];
    out[m] = 1.0f / (1.0f + expf(-v));
}

// ---------------- launch ----------------
extern "C" void kernel_launch(void* const* d_in, const int* in_sizes, int n_in,
                              void* d_out, int out_size) {
    const int*   ei   = (const int*)d_in[0];    // batch1_edge_index [2,E]
    const float* x    = (const float*)d_in[1];  // batch1_x [N,100]
    const float* tE   = (const float*)d_in[4];
    const float* cE   = (const float*)d_in[5];
    const float* pE   = (const float*)d_in[6];
    const float* ghW1 = (const float*)d_in[8];
    const float* ghb1 = (const float*)d_in[9];
    const float* ghW2 = (const float*)d_in[10];
    const float* ghb2 = (const float*)d_in[11];
    const float* mW1  = (const float*)d_in[16];
    const float* mb1  = (const float*)d_in[17];
    const float* mW2  = (const float*)d_in[18];
    const float* mb2  = (const float*)d_in[19];
    const float* mW3  = (const float*)d_in[20];
    const float* mb3  = (const float*)d_in[21];
    // batch2_*, edit_input, gt_* are dead in the reference output — skipped.

    const int* src = ei;
    const int* dst = ei + EE;
    float* out = (float*)d_out;

    k_zero          <<<NN * SHARDS / 256, 256>>>();
    k_hist_gemm     <<<HIST_BLOCKS + GEMM_BLOCKS, 256>>>(dst, x, ghW1);
    k_scan          <<<SCAN_NB, 512>>>();
    k_scatter_scale <<<SCAT_BLOCKS + SCALE_BLOCKS, 256>>>(src, dst);
    k_pass1         <<<NN / 4 / 8, 256>>>(ghb1, ghW2);
    k_pass2         <<<MM / 8, 256>>>(tE, cE, pE, ghb2);
    k_mlp           <<<(MM + 255) / 256, 256>>>(mW1, mb1, mW2, mb2, mW3, mb3, out);
}